// round 1
// baseline (speedup 1.0000x reference)
#include <cuda_runtime.h>

#define N_NODES 100000
#define N_EDGES 3200000

// ---- persistent device scratch (no allocations allowed) ----
__device__ int   g_deg [N_NODES];
__device__ float g_dinv[N_NODES];
__device__ float g_agg1[N_NODES * 4];   // layer-1 aggregated raw features (4-wide)
__device__ float g_t   [N_NODES * 2];   // t = relu(agg1@W1+b1) @ W2  (2-wide)

// Vectorized global reductions (sm_90+): one L2 message per 2/4 floats.
__device__ __forceinline__ void red_add_v4(float* p, float a, float b, float c, float d) {
    asm volatile("red.global.add.v4.f32 [%0], {%1,%2,%3,%4};"
                 :: "l"(p), "f"(a), "f"(b), "f"(c), "f"(d) : "memory");
}
__device__ __forceinline__ void red_add_v2(float* p, float a, float b) {
    asm volatile("red.global.add.v2.f32 [%0], {%1,%2};"
                 :: "l"(p), "f"(a), "f"(b) : "memory");
}

// K0: zero the accumulators
__global__ void k_zero() {
    int i = blockIdx.x * blockDim.x + threadIdx.x;
    if (i < N_NODES) {
        g_deg[i] = 0;
        reinterpret_cast<float4*>(g_agg1)[i] = make_float4(0.f, 0.f, 0.f, 0.f);
    }
}

// K1: degree of dst endpoints (4 edges / thread, int4-coalesced)
__global__ void k_deg(const int* __restrict__ dst) {
    int i = blockIdx.x * blockDim.x + threadIdx.x;
    if (i < N_EDGES / 4) {
        int4 d = reinterpret_cast<const int4*>(dst)[i];
        atomicAdd(&g_deg[d.x], 1);
        atomicAdd(&g_deg[d.y], 1);
        atomicAdd(&g_deg[d.z], 1);
        atomicAdd(&g_deg[d.w], 1);
    }
}

// K2: dinv = rsqrt(deg + 1)   (+1 = self loop; always > 0)
__global__ void k_dinv() {
    int i = blockIdx.x * blockDim.x + threadIdx.x;
    if (i < N_NODES)
        g_dinv[i] = rsqrtf((float)(g_deg[i] + 1));
}

// K3: layer-1 edge aggregation on RAW features: agg1[dst] += x[src] * norm
__global__ void k_l1_edges(const int* __restrict__ src, const int* __restrict__ dst,
                           const float* __restrict__ x) {
    int i = blockIdx.x * blockDim.x + threadIdx.x;
    if (i >= N_EDGES / 4) return;
    int4 s = reinterpret_cast<const int4*>(src)[i];
    int4 d = reinterpret_cast<const int4*>(dst)[i];
    const float4* xv = reinterpret_cast<const float4*>(x);

    #pragma unroll
    for (int k = 0; k < 4; k++) {
        int ss = (k == 0) ? s.x : (k == 1) ? s.y : (k == 2) ? s.z : s.w;
        int dd = (k == 0) ? d.x : (k == 1) ? d.y : (k == 2) ? d.z : d.w;
        float nm = g_dinv[ss] * g_dinv[dd];
        float4 v = xv[ss];
        red_add_v4(&g_agg1[4 * dd], v.x * nm, v.y * nm, v.z * nm, v.w * nm);
    }
}

// K4: per-node transform. a = agg1 + x*dinv^2 (self loop);
//     h = relu(a@W1 + b1); t = h@W2; init out = t*dinv^2 + b2 (self loop of layer 2)
__global__ void k_xform(const float* __restrict__ x,
                        const float* __restrict__ W1, const float* __restrict__ b1,
                        const float* __restrict__ W2, const float* __restrict__ b2,
                        float* __restrict__ out) {
    int v = blockIdx.x * blockDim.x + threadIdx.x;
    if (v >= N_NODES) return;
    float di = g_dinv[v];
    float sl = di * di;                       // self-loop norm
    float4 xv = reinterpret_cast<const float4*>(x)[v];
    float4 ag = reinterpret_cast<const float4*>(g_agg1)[v];
    float a0 = ag.x + xv.x * sl;
    float a1 = ag.y + xv.y * sl;
    float a2 = ag.z + xv.z * sl;
    float a3 = ag.w + xv.w * sl;

    float t0 = 0.f, t1 = 0.f;
    #pragma unroll
    for (int j = 0; j < 16; j++) {
        float h = a0 * W1[j] + a1 * W1[16 + j] + a2 * W1[32 + j] + a3 * W1[48 + j] + b1[j];
        h = fmaxf(h, 0.f);
        t0 += h * W2[2 * j];
        t1 += h * W2[2 * j + 1];
    }
    g_t[2 * v]     = t0;
    g_t[2 * v + 1] = t1;
    // output initialized with self-loop contribution + bias; edges add on top
    out[2 * v]     = t0 * sl + b2[0];
    out[2 * v + 1] = t1 * sl + b2[1];
}

// K5: layer-2 edge aggregation: out[dst] += t[src] * norm
__global__ void k_l2_edges(const int* __restrict__ src, const int* __restrict__ dst,
                           float* __restrict__ out) {
    int i = blockIdx.x * blockDim.x + threadIdx.x;
    if (i >= N_EDGES / 4) return;
    int4 s = reinterpret_cast<const int4*>(src)[i];
    int4 d = reinterpret_cast<const int4*>(dst)[i];
    const float2* tv = reinterpret_cast<const float2*>(g_t);

    #pragma unroll
    for (int k = 0; k < 4; k++) {
        int ss = (k == 0) ? s.x : (k == 1) ? s.y : (k == 2) ? s.z : s.w;
        int dd = (k == 0) ? d.x : (k == 1) ? d.y : (k == 2) ? d.z : d.w;
        float nm = g_dinv[ss] * g_dinv[dd];
        float2 t = tv[ss];
        red_add_v2(&out[2 * dd], t.x * nm, t.y * nm);
    }
}

extern "C" void kernel_launch(void* const* d_in, const int* in_sizes, int n_in,
                              void* d_out, int out_size) {
    const float* x   = (const float*)d_in[0];     // [N, 4]
    const int*   ei  = (const int*)  d_in[1];     // [2, E]
    const float* W1  = (const float*)d_in[2];     // [4, 16]
    const float* b1  = (const float*)d_in[3];     // [16]
    const float* W2  = (const float*)d_in[4];     // [16, 2]
    const float* b2  = (const float*)d_in[5];     // [2]
    float* out = (float*)d_out;                   // [N, 2]

    const int* src = ei;
    const int* dst = ei + N_EDGES;

    const int TB = 256;
    int nodeBlocks = (N_NODES + TB - 1) / TB;
    int edgeBlocks = (N_EDGES / 4 + TB - 1) / TB;

    k_zero    <<<nodeBlocks, TB>>>();
    k_deg     <<<edgeBlocks, TB>>>(dst);
    k_dinv    <<<nodeBlocks, TB>>>();
    k_l1_edges<<<edgeBlocks, TB>>>(src, dst, x);
    k_xform   <<<nodeBlocks, TB>>>(x, W1, b1, W2, b2, out);
    k_l2_edges<<<edgeBlocks, TB>>>(src, dst, out);
}

// round 2
// speedup vs baseline: 1.0016x; 1.0016x over previous
#include <cuda_runtime.h>

#define N_NODES 100000
#define N_EDGES 3200000

// ---- persistent device scratch (no allocations allowed) ----
__device__ int   g_deg [N_NODES];
__device__ float g_dinv[N_NODES];
__device__ float g_agg1[N_NODES * 4];   // layer-1 aggregated raw features (4-wide)
__device__ float g_t   [N_NODES * 2];   // t = relu(agg1@W1+b1) @ W2  (2-wide)

// Vectorized global reductions (sm_90+): one L2 message per 2/4 floats.
__device__ __forceinline__ void red_add_v4(float* p, float a, float b, float c, float d) {
    asm volatile("red.global.add.v4.f32 [%0], {%1,%2,%3,%4};"
                 :: "l"(p), "f"(a), "f"(b), "f"(c), "f"(d) : "memory");
}
__device__ __forceinline__ void red_add_v2(float* p, float a, float b) {
    asm volatile("red.global.add.v2.f32 [%0], {%1,%2};"
                 :: "l"(p), "f"(a), "f"(b) : "memory");
}

// K0: zero the accumulators
__global__ void k_zero() {
    int i = blockIdx.x * blockDim.x + threadIdx.x;
    if (i < N_NODES) {
        g_deg[i] = 0;
        reinterpret_cast<float4*>(g_agg1)[i] = make_float4(0.f, 0.f, 0.f, 0.f);
    }
}

// K1: degree of dst endpoints (4 edges / thread, int4-coalesced)
__global__ void k_deg(const int* __restrict__ dst) {
    int i = blockIdx.x * blockDim.x + threadIdx.x;
    if (i < N_EDGES / 4) {
        int4 d = reinterpret_cast<const int4*>(dst)[i];
        atomicAdd(&g_deg[d.x], 1);
        atomicAdd(&g_deg[d.y], 1);
        atomicAdd(&g_deg[d.z], 1);
        atomicAdd(&g_deg[d.w], 1);
    }
}

// K2: dinv = rsqrt(deg + 1)   (+1 = self loop; always > 0)
__global__ void k_dinv() {
    int i = blockIdx.x * blockDim.x + threadIdx.x;
    if (i < N_NODES)
        g_dinv[i] = rsqrtf((float)(g_deg[i] + 1));
}

// K3: layer-1 edge aggregation on RAW features: agg1[dst] += x[src] * norm
__global__ void k_l1_edges(const int* __restrict__ src, const int* __restrict__ dst,
                           const float* __restrict__ x) {
    int i = blockIdx.x * blockDim.x + threadIdx.x;
    if (i >= N_EDGES / 4) return;
    int4 s = reinterpret_cast<const int4*>(src)[i];
    int4 d = reinterpret_cast<const int4*>(dst)[i];
    const float4* xv = reinterpret_cast<const float4*>(x);

    #pragma unroll
    for (int k = 0; k < 4; k++) {
        int ss = (k == 0) ? s.x : (k == 1) ? s.y : (k == 2) ? s.z : s.w;
        int dd = (k == 0) ? d.x : (k == 1) ? d.y : (k == 2) ? d.z : d.w;
        float nm = g_dinv[ss] * g_dinv[dd];
        float4 v = xv[ss];
        red_add_v4(&g_agg1[4 * dd], v.x * nm, v.y * nm, v.z * nm, v.w * nm);
    }
}

// K4: per-node transform. a = agg1 + x*dinv^2 (self loop);
//     h = relu(a@W1 + b1); t = h@W2; init out = t*dinv^2 + b2 (self loop of layer 2)
__global__ void k_xform(const float* __restrict__ x,
                        const float* __restrict__ W1, const float* __restrict__ b1,
                        const float* __restrict__ W2, const float* __restrict__ b2,
                        float* __restrict__ out) {
    int v = blockIdx.x * blockDim.x + threadIdx.x;
    if (v >= N_NODES) return;
    float di = g_dinv[v];
    float sl = di * di;                       // self-loop norm
    float4 xv = reinterpret_cast<const float4*>(x)[v];
    float4 ag = reinterpret_cast<const float4*>(g_agg1)[v];
    float a0 = ag.x + xv.x * sl;
    float a1 = ag.y + xv.y * sl;
    float a2 = ag.z + xv.z * sl;
    float a3 = ag.w + xv.w * sl;

    float t0 = 0.f, t1 = 0.f;
    #pragma unroll
    for (int j = 0; j < 16; j++) {
        float h = a0 * W1[j] + a1 * W1[16 + j] + a2 * W1[32 + j] + a3 * W1[48 + j] + b1[j];
        h = fmaxf(h, 0.f);
        t0 += h * W2[2 * j];
        t1 += h * W2[2 * j + 1];
    }
    g_t[2 * v]     = t0;
    g_t[2 * v + 1] = t1;
    // output initialized with self-loop contribution + bias; edges add on top
    out[2 * v]     = t0 * sl + b2[0];
    out[2 * v + 1] = t1 * sl + b2[1];
}

// K5: layer-2 edge aggregation: out[dst] += t[src] * norm
__global__ void k_l2_edges(const int* __restrict__ src, const int* __restrict__ dst,
                           float* __restrict__ out) {
    int i = blockIdx.x * blockDim.x + threadIdx.x;
    if (i >= N_EDGES / 4) return;
    int4 s = reinterpret_cast<const int4*>(src)[i];
    int4 d = reinterpret_cast<const int4*>(dst)[i];
    const float2* tv = reinterpret_cast<const float2*>(g_t);

    #pragma unroll
    for (int k = 0; k < 4; k++) {
        int ss = (k == 0) ? s.x : (k == 1) ? s.y : (k == 2) ? s.z : s.w;
        int dd = (k == 0) ? d.x : (k == 1) ? d.y : (k == 2) ? d.z : d.w;
        float nm = g_dinv[ss] * g_dinv[dd];
        float2 t = tv[ss];
        red_add_v2(&out[2 * dd], t.x * nm, t.y * nm);
    }
}

extern "C" void kernel_launch(void* const* d_in, const int* in_sizes, int n_in,
                              void* d_out, int out_size) {
    const float* x   = (const float*)d_in[0];     // [N, 4]
    const int*   ei  = (const int*)  d_in[1];     // [2, E]
    const float* W1  = (const float*)d_in[2];     // [4, 16]
    const float* b1  = (const float*)d_in[3];     // [16]
    const float* W2  = (const float*)d_in[4];     // [16, 2]
    const float* b2  = (const float*)d_in[5];     // [2]
    float* out = (float*)d_out;                   // [N, 2]

    const int* src = ei;
    const int* dst = ei + N_EDGES;

    const int TB = 256;
    int nodeBlocks = (N_NODES + TB - 1) / TB;
    int edgeBlocks = (N_EDGES / 4 + TB - 1) / TB;

    k_zero    <<<nodeBlocks, TB>>>();
    k_deg     <<<edgeBlocks, TB>>>(dst);
    k_dinv    <<<nodeBlocks, TB>>>();
    k_l1_edges<<<edgeBlocks, TB>>>(src, dst, x);
    k_xform   <<<nodeBlocks, TB>>>(x, W1, b1, W2, b2, out);
    k_l2_edges<<<edgeBlocks, TB>>>(src, dst, out);
}

// round 3
// speedup vs baseline: 1.3893x; 1.3871x over previous
#include <cuda_runtime.h>

#define N_NODES 100000
#define N_EDGES 3200000

// ---- persistent device scratch (no allocations allowed) ----
__device__ int   g_deg [N_NODES];
__device__ float g_dinv[N_NODES];
__device__ float g_xn  [N_NODES * 4];   // x * dinv  (src-normalized features)
__device__ float g_agg [N_NODES * 4];   // un-dst-normalized layer-1 aggregate
__device__ float g_tn  [N_NODES * 2];   // t * dinv  (src-normalized layer-2 features)

// Vectorized global reductions (sm_90+): one L2 message per 2/4 floats.
__device__ __forceinline__ void red_add_v4(float* p, float a, float b, float c, float d) {
    asm volatile("red.global.add.v4.f32 [%0], {%1,%2,%3,%4};"
                 :: "l"(p), "f"(a), "f"(b), "f"(c), "f"(d) : "memory");
}
__device__ __forceinline__ void red_add_v2(float* p, float a, float b) {
    asm volatile("red.global.add.v2.f32 [%0], {%1,%2};"
                 :: "l"(p), "f"(a), "f"(b) : "memory");
}

// K0: zero the accumulators
__global__ void k_zero() {
    int i = blockIdx.x * blockDim.x + threadIdx.x;
    if (i < N_NODES) {
        g_deg[i] = 0;
        reinterpret_cast<float4*>(g_agg)[i] = make_float4(0.f, 0.f, 0.f, 0.f);
    }
}

// K1: degree of dst endpoints (4 edges / thread, int4-coalesced)
__global__ void k_deg(const int* __restrict__ dst) {
    int i = blockIdx.x * blockDim.x + threadIdx.x;
    if (i < N_EDGES / 4) {
        int4 d = reinterpret_cast<const int4*>(dst)[i];
        atomicAdd(&g_deg[d.x], 1);
        atomicAdd(&g_deg[d.y], 1);
        atomicAdd(&g_deg[d.z], 1);
        atomicAdd(&g_deg[d.w], 1);
    }
}

// K2: dinv = rsqrt(deg+1);  xn = x * dinv
__global__ void k_dinv_xn(const float* __restrict__ x) {
    int i = blockIdx.x * blockDim.x + threadIdx.x;
    if (i >= N_NODES) return;
    float di = rsqrtf((float)(g_deg[i] + 1));
    g_dinv[i] = di;
    float4 xv = reinterpret_cast<const float4*>(x)[i];
    reinterpret_cast<float4*>(g_xn)[i] =
        make_float4(xv.x * di, xv.y * di, xv.z * di, xv.w * di);
}

// K3: layer-1 edge aggregation: agg[dst] += xn[src]   (dst factor deferred)
__global__ void k_l1_edges(const int* __restrict__ src, const int* __restrict__ dst) {
    int i = blockIdx.x * blockDim.x + threadIdx.x;
    if (i >= N_EDGES / 4) return;
    int4 s = reinterpret_cast<const int4*>(src)[i];
    int4 d = reinterpret_cast<const int4*>(dst)[i];
    const float4* xv = reinterpret_cast<const float4*>(g_xn);

    float4 v0 = xv[s.x];
    float4 v1 = xv[s.y];
    float4 v2 = xv[s.z];
    float4 v3 = xv[s.w];
    red_add_v4(&g_agg[4 * d.x], v0.x, v0.y, v0.z, v0.w);
    red_add_v4(&g_agg[4 * d.y], v1.x, v1.y, v1.z, v1.w);
    red_add_v4(&g_agg[4 * d.z], v2.x, v2.y, v2.z, v2.w);
    red_add_v4(&g_agg[4 * d.w], v3.x, v3.y, v3.z, v3.w);
}

// K4: per-node transform.
//   a  = dinv*agg + x*dinv^2  (apply deferred dst factor; add layer-1 self loop)
//   h  = relu(a@W1 + b1);  t = h@W2;  tn = t*dinv
//   out-accumulator init = tn  (== self-loop contribution pre-dst-scale)
__global__ void k_xform(const float* __restrict__ x,
                        const float* __restrict__ W1, const float* __restrict__ b1,
                        const float* __restrict__ W2,
                        float* __restrict__ out) {
    int v = blockIdx.x * blockDim.x + threadIdx.x;
    if (v >= N_NODES) return;
    float di = g_dinv[v];
    float sl = di * di;
    float4 xv = reinterpret_cast<const float4*>(x)[v];
    float4 ag = reinterpret_cast<const float4*>(g_agg)[v];
    float a0 = ag.x * di + xv.x * sl;
    float a1 = ag.y * di + xv.y * sl;
    float a2 = ag.z * di + xv.z * sl;
    float a3 = ag.w * di + xv.w * sl;

    float t0 = 0.f, t1 = 0.f;
    #pragma unroll
    for (int j = 0; j < 16; j++) {
        float h = a0 * W1[j] + a1 * W1[16 + j] + a2 * W1[32 + j] + a3 * W1[48 + j] + b1[j];
        h = fmaxf(h, 0.f);
        t0 += h * W2[2 * j];
        t1 += h * W2[2 * j + 1];
    }
    float tn0 = t0 * di, tn1 = t1 * di;
    reinterpret_cast<float2*>(g_tn)[v] = make_float2(tn0, tn1);
    reinterpret_cast<float2*>(out)[v]  = make_float2(tn0, tn1);  // self-loop init
}

// K5: layer-2 edge aggregation: out[dst] += tn[src]   (dst factor deferred)
__global__ void k_l2_edges(const int* __restrict__ src, const int* __restrict__ dst,
                           float* __restrict__ out) {
    int i = blockIdx.x * blockDim.x + threadIdx.x;
    if (i >= N_EDGES / 4) return;
    int4 s = reinterpret_cast<const int4*>(src)[i];
    int4 d = reinterpret_cast<const int4*>(dst)[i];
    const float2* tv = reinterpret_cast<const float2*>(g_tn);

    float2 t0 = tv[s.x];
    float2 t1 = tv[s.y];
    float2 t2 = tv[s.z];
    float2 t3 = tv[s.w];
    red_add_v2(&out[2 * d.x], t0.x, t0.y);
    red_add_v2(&out[2 * d.y], t1.x, t1.y);
    red_add_v2(&out[2 * d.z], t2.x, t2.y);
    red_add_v2(&out[2 * d.w], t3.x, t3.y);
}

// K6: apply deferred dst factor + bias:  out = out*dinv + b2
__global__ void k_finish(float* __restrict__ out, const float* __restrict__ b2) {
    int v = blockIdx.x * blockDim.x + threadIdx.x;
    if (v >= N_NODES) return;
    float di = g_dinv[v];
    float2 o = reinterpret_cast<float2*>(out)[v];
    reinterpret_cast<float2*>(out)[v] =
        make_float2(o.x * di + b2[0], o.y * di + b2[1]);
}

extern "C" void kernel_launch(void* const* d_in, const int* in_sizes, int n_in,
                              void* d_out, int out_size) {
    const float* x   = (const float*)d_in[0];     // [N, 4]
    const int*   ei  = (const int*)  d_in[1];     // [2, E]
    const float* W1  = (const float*)d_in[2];     // [4, 16]
    const float* b1  = (const float*)d_in[3];     // [16]
    const float* W2  = (const float*)d_in[4];     // [16, 2]
    const float* b2  = (const float*)d_in[5];     // [2]
    float* out = (float*)d_out;                   // [N, 2]

    const int* src = ei;
    const int* dst = ei + N_EDGES;

    const int TB = 256;
    int nodeBlocks = (N_NODES + TB - 1) / TB;
    int edgeBlocks = (N_EDGES / 4 + TB - 1) / TB;

    k_zero    <<<nodeBlocks, TB>>>();
    k_deg     <<<edgeBlocks, TB>>>(dst);
    k_dinv_xn <<<nodeBlocks, TB>>>(x);
    k_l1_edges<<<edgeBlocks, TB>>>(src, dst);
    k_xform   <<<nodeBlocks, TB>>>(x, W1, b1, W2, out);
    k_l2_edges<<<edgeBlocks, TB>>>(src, dst, out);
    k_finish  <<<nodeBlocks, TB>>>(out, b2);
}